// round 2
// baseline (speedup 1.0000x reference)
#include <cuda_runtime.h>
#include <cstdint>

#define B_SZ  8
#define SEQ   4096
#define HID   1024
#define NGRP  (SEQ / 32)     // 128 t-groups of 32 steps
#define DMAX  64             // FIR truncation: g[d] ~ 0.16^d
#define TC    512            // t-chunk per FIR block

// ---------------- scratch (device globals; no allocation allowed) ----------------
// bit (t&31) of word [b][t>>5][h] = spike(b,t,h). 4 MB.
__device__ unsigned g_bits[B_SZ][NGRP][HID];
__device__ float    g_g[DMAX];          // impulse response C A^d B
__device__ float    g_u[B_SZ][SEQ];     // u[b][t]
__device__ float    g_y[B_SZ][SEQ];     // y[b][t]

// ---------------- pass 1: LIF neurons -> spike bitmasks --------------------------
// One thread per (b,h) lane; 4096-step recursion, distance-2 register prefetch,
// branch-speculated update so the critical chain is FSETP -> select only.
__global__ void __launch_bounds__(64, 1) snn_kernel(const float* __restrict__ x)
{
    const int blk  = blockIdx.x;        // 0..127
    const int b    = blk >> 4;          // 16 blocks per batch
    const int tid  = threadIdx.x;       // 0..63
    const int h    = (blk & 15) * 64 + tid;

    const float* xp = x + (size_t)b * SEQ * HID + h;
    unsigned* sb = &g_bits[b][0][h];    // stride HID words per t-group

    float xbuf[2][32];
    #pragma unroll
    for (int i = 0; i < 32; i++) xbuf[0][i] = xp[(size_t)i * HID];
    #pragma unroll
    for (int i = 0; i < 32; i++) xbuf[1][i] = xp[(size_t)(32 + i) * HID];

    // Invariant entering step k: w = w_{k-1} (pre-reset membrane), sp = spike_{k-1},
    // r = r_{k-1}, c = (r_{k-2} <= 1)  [so active_k = !sp && c],
    // q = (max(r_{k-2}-1,0) <= 1)      [so next c = !sp && q = (r_{k-1} <= 1)].
    float w = 0.0f, r = 0.0f;
    bool  sp = false, c = true, q = true;

    #pragma unroll 2
    for (int cg = 0; cg < NGRP; cg++) {
        const int  cur = cg & 1;
        const bool pf  = (cg < NGRP - 2);
        const int  tpf = (cg + 2) * 32;
        unsigned mask = 0;

        #pragma unroll
        for (int i = 0; i < 32; i++) {
            float xk = xbuf[cur][i];
            if (pf) xbuf[cur][i] = xp[(size_t)(tpf + i) * HID];  // prefetch cg+2

            // speculative membrane: both branches before spike pred resolves
            float A  = __fadd_rn(__fmul_rn(w, 0.9f), xk);  // no-spike candidate
            bool  cn = (!sp) && q;          // c_{k+1} = (r_{k-1} <= 1)
            bool  p  = (A >= 1.0f) && c;    // speculative spike (valid if !sp)
            bool  spn = (!sp) && p;         // spike_k
            w = sp ? xk : A;                // w_k  (spike => 0.9*0+x = x, bit-exact)

            float rd = fmaxf(__fadd_rn(r, -1.0f), 0.0f);
            bool  qn = (rd <= 1.0f);
            r = spn ? 5.0f : rd;            // r_k

            mask |= spn ? (1u << i) : 0u;
            sp = spn; c = cn; q = qn;
        }
        sb[(size_t)cg * HID] = mask;        // coalesced: consecutive h
    }
}

// ---------------- pass 2a: impulse response g[d] = C * A^d * B -------------------
__global__ void g_kernel(const float* __restrict__ A,
                         const float* __restrict__ Bv,
                         const float* __restrict__ Cv)
{
    __shared__ float As[64 * 65];
    __shared__ float Wd[64 * 65];
    __shared__ float ws[64];
    __shared__ float cs[64];

    const int tid = threadIdx.x;    // 64 threads
    for (int i = tid; i < 64 * 64; i += 64) {
        int n = i >> 6, s = i & 63;
        As[n * 65 + s] = A[i];
    }
    cs[tid] = Cv[tid];
    float w0 = Bv[tid];
    ws[tid] = w0;
    Wd[tid] = w0;
    __syncthreads();

    for (int d = 1; d < DMAX; d++) {
        float a0 = 0.f, a1 = 0.f, a2 = 0.f, a3 = 0.f;
        #pragma unroll
        for (int s = 0; s < 64; s += 4) {
            a0 += As[tid * 65 + s + 0] * ws[s + 0];
            a1 += As[tid * 65 + s + 1] * ws[s + 1];
            a2 += As[tid * 65 + s + 2] * ws[s + 2];
            a3 += As[tid * 65 + s + 3] * ws[s + 3];
        }
        float wn = (a0 + a1) + (a2 + a3);
        __syncthreads();
        ws[tid] = wn;
        Wd[d * 65 + tid] = wn;
        __syncthreads();
    }
    float acc = 0.f;
    #pragma unroll
    for (int j = 0; j < 64; j++) acc += cs[j] * Wd[tid * 65 + j];
    g_g[tid] = acc;
}

// ---------------- pass 2b: u[b][t] = popcount over h / 1024 ----------------------
// grid: B_SZ*8 blocks, 256 threads; each block does 16 t-groups of one batch.
__global__ void u_kernel()
{
    __shared__ unsigned wsm[HID];
    __shared__ int part[8 * 32];

    const int b   = blockIdx.x >> 3;
    const int g0  = (blockIdx.x & 7) * 16;
    const int tid = threadIdx.x;
    const int wid = tid >> 5, lane = tid & 31;

    for (int j = 0; j < 16; j++) {
        const int g = g0 + j;
        ((uint4*)wsm)[tid] = ((const uint4*)&g_bits[b][g][0])[tid];
        __syncthreads();

        int cnt = 0;
        #pragma unroll 8
        for (int i = 0; i < 128; i++) {
            unsigned wd = wsm[wid * 128 + i];   // broadcast within warp
            cnt += (int)((wd >> lane) & 1u);
        }
        part[wid * 32 + lane] = cnt;
        __syncthreads();

        if (tid < 32) {
            int tot = 0;
            #pragma unroll
            for (int ww = 0; ww < 8; ww++) tot += part[ww * 32 + tid];
            g_u[b][g * 32 + tid] = (float)tot * (1.0f / (float)HID);
        }
        __syncthreads();
    }
}

// ---------------- pass 2c: y = D*u + g (*) u (64-tap causal FIR) ------------------
__global__ void y_kernel(const float* __restrict__ Dp)
{
    __shared__ float u_s[TC + DMAX];
    __shared__ float g_s[DMAX];

    const int b     = blockIdx.x >> 3;      // SEQ/TC = 8 chunks per batch
    const int t0    = (blockIdx.x & 7) * TC;
    const int tid   = threadIdx.x;          // 256

    if (tid < DMAX) g_s[tid] = g_g[tid];

    for (int i = tid; i < TC + DMAX - 1; i += 256) {
        int t = t0 + i - (DMAX - 1);
        u_s[i] = (t >= 0) ? g_u[b][t] : 0.0f;
    }
    __syncthreads();

    const float Ds = *Dp;
    for (int i = tid; i < TC; i += 256) {
        float acc = Ds * u_s[i + DMAX - 1];
        #pragma unroll
        for (int d = 0; d < DMAX; d++)
            acc += g_s[d] * u_s[i + DMAX - 1 - d];
        g_y[b][t0 + i] = acc;
    }
}

// ---------------- pass 3: out[b][t][h] = spike_bit + y[b][t] ---------------------
// grid: B_SZ * NGRP blocks; block covers 32 t x 1024 h = 128 KB of output.
__global__ void __launch_bounds__(256) out_kernel(float4* __restrict__ out)
{
    __shared__ float ys[32], ys1[32];

    const int b   = blockIdx.x >> 7;
    const int g   = blockIdx.x & (NGRP - 1);
    const int tid = threadIdx.x;            // h4 = tid: hidden 4*tid..4*tid+3

    if (tid < 32) {
        float yv = g_y[b][g * 32 + tid];
        ys[tid]  = yv;
        ys1[tid] = yv + 1.0f;
    }
    const uint4 wv = ((const uint4*)&g_bits[b][g][0])[tid];
    __syncthreads();

    float4* base = out + ((size_t)(b * SEQ + g * 32) * HID) / 4 + tid;
    #pragma unroll
    for (int t = 0; t < 32; t++) {
        const float y  = ys[t];
        const float y1 = ys1[t];
        float4 o;
        o.x = (wv.x & (1u << t)) ? y1 : y;
        o.y = (wv.y & (1u << t)) ? y1 : y;
        o.z = (wv.z & (1u << t)) ? y1 : y;
        o.w = (wv.w & (1u << t)) ? y1 : y;
        base[(size_t)t * (HID / 4)] = o;
    }
}

// ---------------- launch ----------------------------------------------------------
extern "C" void kernel_launch(void* const* d_in, const int* in_sizes, int n_in,
                              void* d_out, int out_size)
{
    const float* x  = (const float*)d_in[0];   // (8, 4096, 1024) f32
    const float* A  = (const float*)d_in[1];   // (64, 64)
    const float* Bv = (const float*)d_in[2];   // (64, 1)
    const float* Cv = (const float*)d_in[3];   // (1, 64)
    const float* Dp = (const float*)d_in[4];   // (1, 1)

    snn_kernel<<<128, 64>>>(x);
    g_kernel<<<1, 64>>>(A, Bv, Cv);
    u_kernel<<<B_SZ * 8, 256>>>();
    y_kernel<<<B_SZ * (SEQ / TC), 256>>>(Dp);
    out_kernel<<<B_SZ * NGRP, 256>>>((float4*)d_out);
}

// round 3
// speedup vs baseline: 1.7376x; 1.7376x over previous
#include <cuda_runtime.h>
#include <cstdint>

#define B_SZ  8
#define SEQ   4096
#define HID   1024
#define NGRP  (SEQ / 32)     // 128 t-groups of 32 steps
#define DMAX  64             // FIR truncation: g[d] ~ 0.16^d
#define CHUNKS 4             // time-chunks for the SNN scan
#define CGRP   (NGRP / CHUNKS)  // 32 stored groups per chunk
#define WGRP   10            // warmup groups (320 steps): 0.9^320 ~ 4e-16
#define YC     256           // t-chunk per fused u+y block

// ---------------- scratch (device globals; no allocation allowed) ----------------
// bit (t&31) of word [b][t>>5][h] = spike(b,t,h). 4 MB.
__device__ unsigned g_bits[B_SZ][NGRP][HID];
__device__ float    g_g[DMAX];          // impulse response C A^d B
__device__ float    g_y[B_SZ][SEQ];     // y[b][t]

// ---------------- pass 1: LIF neurons -> spike bitmasks (+hidden g block) --------
// 512 snn blocks: (b, hblk, chunk), 64 threads; each thread owns one (b,h) lane
// for one time-chunk (320-step warmup reconverges the state). Block 512 computes
// the SSM impulse response g[d] = C A^d B concurrently (hidden under snn).
__global__ void __launch_bounds__(64) snn_kernel(const float* __restrict__ x,
                                                 const float* __restrict__ Ap,
                                                 const float* __restrict__ Bp,
                                                 const float* __restrict__ Cp)
{
    __shared__ float As[64 * 65];
    __shared__ float ws[64];
    __shared__ float red[2];

    if (blockIdx.x >= B_SZ * 16 * CHUNKS) {
        // ---- g block: g[d] = C . (A^d B), d = 0..63 ----
        const int tid = threadIdx.x;      // 64 threads, state index n = tid
        for (int i = tid; i < 64 * 64; i += 64)
            As[(i >> 6) * 65 + (i & 63)] = Ap[i];
        const float cv = Cp[tid];
        float w = Bp[tid];
        ws[tid] = w;
        __syncthreads();
        for (int d = 0; d < DMAX; d++) {
            float p = cv * w;
            #pragma unroll
            for (int o = 16; o; o >>= 1) p += __shfl_down_sync(0xffffffffu, p, o);
            if ((tid & 31) == 0) red[tid >> 5] = p;
            __syncthreads();
            if (tid == 0) g_g[d] = red[0] + red[1];
            if (d < DMAX - 1) {
                float a0 = 0.f, a1 = 0.f, a2 = 0.f, a3 = 0.f;
                #pragma unroll
                for (int s = 0; s < 64; s += 4) {
                    a0 += As[tid * 65 + s + 0] * ws[s + 0];
                    a1 += As[tid * 65 + s + 1] * ws[s + 1];
                    a2 += As[tid * 65 + s + 2] * ws[s + 2];
                    a3 += As[tid * 65 + s + 3] * ws[s + 3];
                }
                float wn = (a0 + a1) + (a2 + a3);
                __syncthreads();
                ws[tid] = wn;
                __syncthreads();
                w = wn;
            }
        }
        return;
    }

    // ---- SNN path ----
    const int blk  = blockIdx.x;          // 0..511
    const int c    = blk & (CHUNKS - 1);
    const int hblk = (blk >> 2) & 15;
    const int b    = blk >> 6;
    const int tid  = threadIdx.x;
    const int h    = hblk * 64 + tid;

    const int warm    = (c == 0) ? 0 : WGRP;
    const int g0      = c * CGRP;         // first stored group
    const int tbegin  = g0 * 32 - warm * 32;
    const int ngroups = warm + CGRP;

    const float* xp = x + ((size_t)b * SEQ + tbegin) * HID + h;
    unsigned* sb = &g_bits[b][g0][h];

    float xbuf[2][32];
    #pragma unroll
    for (int i = 0; i < 32; i++) xbuf[0][i] = xp[(size_t)i * HID];
    #pragma unroll
    for (int i = 0; i < 32; i++) xbuf[1][i] = xp[(size_t)(32 + i) * HID];

    float w = 0.0f, r = 0.0f;
    bool  sp = false, cc = true, q = true;

    for (int gg = 0; gg < ngroups; gg++) {
        const int  cur = gg & 1;
        const bool pf  = (gg < ngroups - 2);
        const int  tpf = (gg + 2) * 32;
        unsigned mask = 0;

        #pragma unroll
        for (int i = 0; i < 32; i++) {
            float xk = xbuf[cur][i];
            if (pf) xbuf[cur][i] = xp[(size_t)(tpf + i) * HID];  // prefetch gg+2

            float Av  = __fadd_rn(__fmul_rn(w, 0.9f), xk);  // no-spike candidate
            bool  cn  = (!sp) && q;
            bool  pbt = (Av >= 1.0f) && cc;
            bool  spn = (!sp) && pbt;       // spike_k
            w = sp ? xk : Av;               // spike => v was 0 => 0.9*0+x = x
            float rd = fmaxf(__fadd_rn(r, -1.0f), 0.0f);
            bool  qn = (rd <= 1.0f);
            r = spn ? 5.0f : rd;
            mask |= spn ? (1u << i) : 0u;
            sp = spn; cc = cn; q = qn;
        }
        if (gg >= warm) sb[(size_t)(gg - warm) * HID] = mask;   // coalesced
    }
}

// ---------------- pass 2: fused u (popcount transpose) + y (64-tap FIR) ----------
// grid: B_SZ*16 blocks, 256 threads; block (b,yc) produces y[b][yc*256 .. +256).
__global__ void __launch_bounds__(256) uy_kernel(const float* __restrict__ Dp)
{
    __shared__ unsigned wsm[HID];
    __shared__ int   part[8 * 32];
    __shared__ float u_s[64 + YC];   // u_s[i] = u[t0 - 64 + i]
    __shared__ float g_s[DMAX];

    const int b   = blockIdx.x >> 4;
    const int yc  = blockIdx.x & 15;
    const int t0  = yc * YC;
    const int gb  = yc * (YC / 32);
    const int tid = threadIdx.x;
    const int wid = tid >> 5, lane = tid & 31;

    if (tid < DMAX) g_s[tid] = g_g[tid];

    for (int j = -2; j < YC / 32; j++) {        // 2 halo groups + 8 own groups
        const int g  = gb + j;
        const int i0 = 64 + j * 32;
        if (g < 0) {                            // uniform across block
            if (tid < 32) u_s[i0 + tid] = 0.0f;
            continue;
        }
        ((uint4*)wsm)[tid] = ((const uint4*)&g_bits[b][g][0])[tid];
        __syncthreads();
        int cnt = 0;
        #pragma unroll 8
        for (int i2 = 0; i2 < 128; i2++)
            cnt += (int)((wsm[wid * 128 + i2] >> lane) & 1u);
        part[wid * 32 + lane] = cnt;
        __syncthreads();
        if (tid < 32) {
            int tot = 0;
            #pragma unroll
            for (int ww = 0; ww < 8; ww++) tot += part[ww * 32 + tid];
            u_s[i0 + tid] = (float)tot * (1.0f / (float)HID);
        }
        __syncthreads();
    }

    const float Ds = *Dp;
    // y[t] = D*u[t] + sum_{d=0}^{63} g[d] * u[t-d]
    {
        const int i = tid;                      // YC == blockDim.x
        float acc = Ds * u_s[64 + i];
        #pragma unroll
        for (int d = 0; d < DMAX; d++)
            acc += g_s[d] * u_s[64 + i - d];
        g_y[b][t0 + i] = acc;
    }
}

// ---------------- pass 3: out[b][t][h] = spike_bit + y[b][t] ---------------------
// grid: B_SZ * NGRP * 2 blocks; block covers 16 t x 1024 h (64 KB of output).
__global__ void __launch_bounds__(256) out_kernel(float4* __restrict__ out)
{
    __shared__ float ys[16], ys1[16];

    const int blk  = blockIdx.x;
    const int half = blk & 1;
    const int g    = (blk >> 1) & (NGRP - 1);
    const int b    = blk >> 8;
    const int tid  = threadIdx.x;            // h4 = tid: hidden 4*tid..4*tid+3

    if (tid < 16) {
        float yv = g_y[b][g * 32 + half * 16 + tid];
        ys[tid]  = yv;
        ys1[tid] = yv + 1.0f;
    }
    const uint4 wv = ((const uint4*)&g_bits[b][g][0])[tid];
    __syncthreads();

    float4* base = out + ((size_t)(b * SEQ + g * 32 + half * 16) * HID) / 4 + tid;
    #pragma unroll
    for (int t = 0; t < 16; t++) {
        const unsigned bit = 1u << (half * 16 + t);
        const float y  = ys[t];
        const float y1 = ys1[t];
        float4 o;
        o.x = (wv.x & bit) ? y1 : y;
        o.y = (wv.y & bit) ? y1 : y;
        o.z = (wv.z & bit) ? y1 : y;
        o.w = (wv.w & bit) ? y1 : y;
        __stcs(&base[(size_t)t * (HID / 4)], o);
    }
}

// ---------------- launch ----------------------------------------------------------
extern "C" void kernel_launch(void* const* d_in, const int* in_sizes, int n_in,
                              void* d_out, int out_size)
{
    const float* x  = (const float*)d_in[0];   // (8, 4096, 1024) f32
    const float* A  = (const float*)d_in[1];   // (64, 64)
    const float* Bv = (const float*)d_in[2];   // (64, 1)
    const float* Cv = (const float*)d_in[3];   // (1, 64)
    const float* Dp = (const float*)d_in[4];   // (1, 1)

    snn_kernel<<<B_SZ * 16 * CHUNKS + 1, 64>>>(x, A, Bv, Cv);
    uy_kernel<<<B_SZ * 16, 256>>>(Dp);
    out_kernel<<<B_SZ * NGRP * 2, 256>>>((float4*)d_out);
}